// round 2
// baseline (speedup 1.0000x reference)
#include <cuda_runtime.h>

#define NOUT 48
#define CIN 384
#define NPIX 35200       // ny*nx = 200*176
#define NB 4
#define TOTAL_PIX (NB * NPIX)   // 140800

// ---- packed f32x2 helpers (sm_103a) ----
__device__ __forceinline__ unsigned long long pack2(float lo, float hi) {
    unsigned long long r;
    asm("mov.b64 %0, {%1, %2};" : "=l"(r) : "f"(lo), "f"(hi));
    return r;
}
__device__ __forceinline__ void unpack2(unsigned long long v, float& lo, float& hi) {
    asm("mov.b64 {%0, %1}, %2;" : "=f"(lo), "=f"(hi) : "l"(v));
}
__device__ __forceinline__ void ffma2(unsigned long long& d,
                                      unsigned long long a,
                                      unsigned long long b) {
    asm("fma.rn.f32x2 %0, %1, %2, %0;" : "+l"(d) : "l"(a), "l"(b));
}

extern __shared__ float s_buf[];   // [CIN*NOUT] transposed weights, then [NOUT] bias

__global__ __launch_bounds__(256)
void proposal_kernel(const float* __restrict__ feat,
                     const float* __restrict__ Wc,
                     const float* __restrict__ bc,
                     const float* __restrict__ Wr,
                     const float* __restrict__ br,
                     float* __restrict__ out)
{
    float* ws = s_buf;               // ws[c*48 + o] = W[o][c], o<6 -> Wc, else Wr
    float* bs = s_buf + CIN * NOUT;  // bs[o]

    const int tid = threadIdx.x;

    // cooperative transposed weight load (one-time per block; weights are tiny & L2-hot)
    for (int i = tid; i < CIN * NOUT; i += blockDim.x) {
        const int c = i / NOUT;
        const int o = i % NOUT;
        ws[i] = (o < 6) ? Wc[o * CIN + c] : Wr[(o - 6) * CIN + c];
    }
    if (tid < NOUT) bs[tid] = (tid < 6) ? bc[tid] : br[tid - 6];
    __syncthreads();

    const int gt = blockIdx.x * blockDim.x + tid;  // one pixel per thread, grid exact
    const int b  = gt / NPIX;
    const int p  = gt % NPIX;

    // 24 packed accumulators: acc[q] = outputs (2q, 2q+1) for this pixel
    unsigned long long acc[NOUT / 2];
#pragma unroll
    for (int q = 0; q < NOUT / 2; q++) acc[q] = pack2(bs[2 * q], bs[2 * q + 1]);

    const float* fb = feat + (long)b * CIN * NPIX + p;

#pragma unroll 4
    for (int c = 0; c < CIN; c++) {
        const float f = fb[(long)c * NPIX];           // warp-coalesced 128B line
        const unsigned long long fa = pack2(f, f);    // one pack per channel
        const ulonglong2* wrow = (const ulonglong2*)(ws + c * NOUT);  // broadcast LDS.128
#pragma unroll
        for (int q2 = 0; q2 < 12; q2++) {             // 12 x ulonglong2 = all 48 channels
            const ulonglong2 w2 = wrow[q2];           // (w[4q2],w[4q2+1]) , (w[4q2+2],w[4q2+3])
            ffma2(acc[2 * q2 + 0], fa, w2.x);
            ffma2(acc[2 * q2 + 1], fa, w2.y);
        }
    }

    // ---- cls: out[(b*6 + o)*NPIX + p], o in [0,6) = pairs q=0..2 ----
#pragma unroll
    for (int q = 0; q < 3; q++) {
        float lo, hi;
        unpack2(acc[q], lo, hi);
        out[((long)b * 6 + (2 * q + 0)) * NPIX + p] = lo;
        out[((long)b * 6 + (2 * q + 1)) * NPIX + p] = hi;
    }

    // ---- reg: permuted layout (B, 3, 2, ny, nx, 7) ----
    // reg_raw channel o_r = c3*14 + d*2 + y  (combined o = 6 + o_r)
    // packed pair index q = 3 + c3*7 + d holds (y=0 in lo, y=1 in hi)
    float* outr = out + (long)NB * 6 * NPIX;   // 844800
#pragma unroll
    for (int c3 = 0; c3 < 3; c3++) {
        const long base0 = ((((long)b * 3 + c3) * 2 + 0) * NPIX + p) * 7;
        const long base1 = ((((long)b * 3 + c3) * 2 + 1) * NPIX + p) * 7;
#pragma unroll
        for (int d = 0; d < 7; d++) {
            float lo, hi;
            unpack2(acc[3 + c3 * 7 + d], lo, hi);
            outr[base0 + d] = lo;   // y = 0
            outr[base1 + d] = hi;   // y = 1
        }
    }
}

extern "C" void kernel_launch(void* const* d_in, const int* in_sizes, int n_in,
                              void* d_out, int out_size)
{
    const float* feat = (const float*)d_in[0];
    const float* Wc   = (const float*)d_in[1];
    const float* bc   = (const float*)d_in[2];
    const float* Wr   = (const float*)d_in[3];
    const float* br   = (const float*)d_in[4];
    float* out = (float*)d_out;

    const int smem_bytes = (CIN * NOUT + NOUT) * (int)sizeof(float);  // 73920 B
    cudaFuncSetAttribute(proposal_kernel,
                         cudaFuncAttributeMaxDynamicSharedMemorySize, smem_bytes);

    const int threads = 256;
    const int blocks  = TOTAL_PIX / threads;   // 550, exact
    proposal_kernel<<<blocks, threads, smem_bytes>>>(feat, Wc, bc, Wr, br, out);
}